// round 10
// baseline (speedup 1.0000x reference)
#include <cuda_runtime.h>
#include <cuda_bf16.h>
#include <cstdint>

#define EMBED 1024
#define SEQ   2048
#define BATCH 4
#define HEADS 16
#define HDIM  64
#define MTOT  (BATCH * SEQ)          // 8192 rows
#define RSQKV (3 * EMBED)            // qkv row stride (elements)

// ---------------- scratch (static device globals; allocation-free) ----------
__device__ __nv_bfloat16  g_Ah[(size_t)MTOT * EMBED];           // hs split hi
__device__ __nv_bfloat16  g_Al[(size_t)MTOT * EMBED];           // hs split lo
__device__ __nv_bfloat16  g_Wqh[(size_t)3 * EMBED * EMBED];     // qkv W^T hi [N][K]
__device__ __nv_bfloat16  g_Wql[(size_t)3 * EMBED * EMBED];
__device__ __nv_bfloat16  g_Wph[(size_t)EMBED * EMBED];         // proj W^T hi
__device__ __nv_bfloat16  g_Wpl[(size_t)EMBED * EMBED];
__device__ __nv_bfloat16  g_QKVh[(size_t)MTOT * 3 * EMBED];     // qkv split hi
__device__ __nv_bfloat16  g_QKVl[(size_t)MTOT * 3 * EMBED];     // qkv split lo
__device__ __nv_bfloat16  g_Xh[(size_t)MTOT * EMBED];           // attn out hi
__device__ __nv_bfloat16  g_Xl[(size_t)MTOT * EMBED];           // attn out lo

// ---------------- helpers ----------------------------------------------------
__device__ __forceinline__ uint32_t smem_u32(const void* p) {
    uint32_t a;
    asm("{ .reg .u64 t; cvta.to.shared.u64 t, %1; cvt.u32.u64 %0, t; }" : "=r"(a) : "l"(p));
    return a;
}
#define CP_ASYNC16(dst, src) \
    asm volatile("cp.async.cg.shared.global [%0], [%1], 16;" :: "r"(dst), "l"(src))
#define CP_COMMIT() asm volatile("cp.async.commit_group;")
#define CP_WAIT(n)  asm volatile("cp.async.wait_group %0;" :: "n"(n))

__device__ __forceinline__ void ldsm_x4(uint32_t* r, uint32_t addr) {
    asm volatile("ldmatrix.sync.aligned.m8n8.x4.shared.b16 {%0,%1,%2,%3}, [%4];"
                 : "=r"(r[0]), "=r"(r[1]), "=r"(r[2]), "=r"(r[3]) : "r"(addr));
}
__device__ __forceinline__ void ldsm_x2(uint32_t* r, uint32_t addr) {
    asm volatile("ldmatrix.sync.aligned.m8n8.x2.shared.b16 {%0,%1}, [%2];"
                 : "=r"(r[0]), "=r"(r[1]) : "r"(addr));
}
__device__ __forceinline__ void ldsm_x2_t(uint32_t* r, uint32_t addr) {
    asm volatile("ldmatrix.sync.aligned.m8n8.x2.trans.shared.b16 {%0,%1}, [%2];"
                 : "=r"(r[0]), "=r"(r[1]) : "r"(addr));
}
__device__ __forceinline__ void mma_bf16(float* d, const uint32_t* a, const uint32_t* b) {
    asm volatile("mma.sync.aligned.m16n8k16.row.col.f32.bf16.bf16.f32 "
                 "{%0,%1,%2,%3}, {%4,%5,%6,%7}, {%8,%9}, {%0,%1,%2,%3};"
                 : "+f"(d[0]), "+f"(d[1]), "+f"(d[2]), "+f"(d[3])
                 : "r"(a[0]), "r"(a[1]), "r"(a[2]), "r"(a[3]), "r"(b[0]), "r"(b[1]));
}
__device__ __forceinline__ float ex2f(float x) {
    float y; asm("ex2.approx.f32 %0, %1;" : "=f"(y) : "f"(x)); return y;
}
// pack {lo=a, hi=b} fp32 -> bf16x2
__device__ __forceinline__ uint32_t pack_bf2(float a, float b) {
    uint32_t r; asm("cvt.rn.bf16x2.f32 %0, %1, %2;" : "=r"(r) : "f"(b), "f"(a)); return r;
}
__device__ __forceinline__ float bf16_rt(float v) {   // round-trip through bf16
    return __bfloat162float(__float2bfloat16(v));
}

// ---------------------------------------------------------------------------
// split fp32 -> bf16 hi/lo
// ---------------------------------------------------------------------------
__global__ void split_f32(const float* __restrict__ x, __nv_bfloat16* __restrict__ hi,
                          __nv_bfloat16* __restrict__ lo, int n4)
{
    int i = blockIdx.x * blockDim.x + threadIdx.x;
    int stride = gridDim.x * blockDim.x;
    for (; i < n4; i += stride) {
        float4 v = ((const float4*)x)[i];
        __nv_bfloat16 h0 = __float2bfloat16(v.x), h1 = __float2bfloat16(v.y);
        __nv_bfloat16 h2 = __float2bfloat16(v.z), h3 = __float2bfloat16(v.w);
        __nv_bfloat16 l0 = __float2bfloat16(v.x - __bfloat162float(h0));
        __nv_bfloat16 l1 = __float2bfloat16(v.y - __bfloat162float(h1));
        __nv_bfloat16 l2 = __float2bfloat16(v.z - __bfloat162float(h2));
        __nv_bfloat16 l3 = __float2bfloat16(v.w - __bfloat162float(h3));
        ((ushort4*)hi)[i] = make_ushort4(__bfloat16_as_ushort(h0), __bfloat16_as_ushort(h1),
                                         __bfloat16_as_ushort(h2), __bfloat16_as_ushort(h3));
        ((ushort4*)lo)[i] = make_ushort4(__bfloat16_as_ushort(l0), __bfloat16_as_ushort(l1),
                                         __bfloat16_as_ushort(l2), __bfloat16_as_ushort(l3));
    }
}

// ---------------------------------------------------------------------------
// transpose + split: W[K][N] fp32 -> Wt_hi/lo[N][K] bf16
// ---------------------------------------------------------------------------
__global__ void transpose_split(const float* __restrict__ W, __nv_bfloat16* __restrict__ Th,
                                __nv_bfloat16* __restrict__ Tl, int K, int N)
{
    __shared__ float t[32][33];
    int tx = threadIdx.x, ty = threadIdx.y;
#pragma unroll
    for (int j = 0; j < 4; j++) {
        int k = blockIdx.y * 32 + ty + j * 8;
        int n = blockIdx.x * 32 + tx;
        t[ty + j * 8][tx] = W[(size_t)k * N + n];
    }
    __syncthreads();
#pragma unroll
    for (int j = 0; j < 4; j++) {
        int n = blockIdx.x * 32 + ty + j * 8;
        int k = blockIdx.y * 32 + tx;
        float v = t[tx][ty + j * 8];
        __nv_bfloat16 h = __float2bfloat16(v);
        __nv_bfloat16 l = __float2bfloat16(v - __bfloat162float(h));
        Th[(size_t)n * K + k] = h;
        Tl[(size_t)n * K + k] = l;
    }
}

// ---------------------------------------------------------------------------
// bf16-split HMMA GEMM core. block tile 128x256x32, 256 thr (8 warps 2x4),
// warp tile 64x64. 3-stage cp.async pipeline, single sync per K-iter.
// EPI=0: fp32 out + bias.  EPI=1: bf16 hi/lo split out + bias.
// smem stage: Ah 8K | Al 8K | Bh 16K | Bl 16K = 48K; 3 stages = 144K.
// ---------------------------------------------------------------------------
#define SM_AH 0
#define SM_AL 8192
#define SM_BH 16384
#define SM_BL 32768
#define GSTAGE 49152
#define GSMEM  (3 * GSTAGE)

__device__ __forceinline__ void gemm_load_stage(
    const __nv_bfloat16* __restrict__ Ah, const __nv_bfloat16* __restrict__ Al,
    const __nv_bfloat16* __restrict__ Bh, const __nv_bfloat16* __restrict__ Bl,
    int K, int k0, uint32_t sdst, int tid)
{
    // A part: 1024 chunks (Ah 512, Al 512)
#pragma unroll
    for (int i = 0; i < 4; i++) {
        int idx = i * 256 + tid;          // 0..1023
        const __nv_bfloat16* src = (idx >> 9) ? Al : Ah;
        uint32_t base = (idx >> 9) ? (uint32_t)SM_AL : (uint32_t)SM_AH;
        int r = (idx >> 2) & 127;
        int c = idx & 3;
        const char* g = (const char*)(src + (size_t)r * K + k0) + c * 16;
        CP_ASYNC16(sdst + base + r * 64 + ((c ^ ((r >> 1) & 3)) << 4), g);
    }
    // B part: 2048 chunks (Bh 1024, Bl 1024)
#pragma unroll
    for (int i = 0; i < 8; i++) {
        int idx = i * 256 + tid;          // 0..2047
        const __nv_bfloat16* src = (idx >> 10) ? Bl : Bh;
        uint32_t base = (idx >> 10) ? (uint32_t)SM_BL : (uint32_t)SM_BH;
        int r = (idx >> 2) & 255;
        int c = idx & 3;
        const char* g = (const char*)(src + (size_t)r * K + k0) + c * 16;
        CP_ASYNC16(sdst + base + r * 64 + ((c ^ ((r >> 1) & 3)) << 4), g);
    }
}

template <int EPI>
__device__ __forceinline__ void gemm_body(
    const __nv_bfloat16* __restrict__ Ah, const __nv_bfloat16* __restrict__ Al,
    const __nv_bfloat16* __restrict__ Bh, const __nv_bfloat16* __restrict__ Bl,
    const float* __restrict__ bias, float* __restrict__ C,
    __nv_bfloat16* __restrict__ Ch, __nv_bfloat16* __restrict__ Cl, int N, int K)
{
    extern __shared__ char smem[];
    uint32_t sb = smem_u32(smem);
    const int tid  = threadIdx.x;
    const int warp = tid >> 5, lane = tid & 31;
    const int wm = warp >> 2, wn = warp & 3;     // 2 x 4 warp grid, tile 64x64

    const int m0 = blockIdx.y * 128;
    const int n0 = blockIdx.x * 256;
    const __nv_bfloat16* Ah0 = Ah + (size_t)m0 * K;
    const __nv_bfloat16* Al0 = Al + (size_t)m0 * K;
    const __nv_bfloat16* Bh0 = Bh + (size_t)n0 * K;
    const __nv_bfloat16* Bl0 = Bl + (size_t)n0 * K;

    float acc[4][8][4];
#pragma unroll
    for (int i = 0; i < 4; i++)
#pragma unroll
        for (int j = 0; j < 8; j++)
#pragma unroll
            for (int k = 0; k < 4; k++) acc[i][j][k] = 0.f;

    const int iters = K >> 5;
    gemm_load_stage(Ah0, Al0, Bh0, Bl0, K, 0, sb, tid);
    CP_COMMIT();
    gemm_load_stage(Ah0, Al0, Bh0, Bl0, K, 32, sb + GSTAGE, tid);
    CP_COMMIT();

    const int a_r = lane & 15;
    const int a_h = lane >> 4;
    const int b_r = ((lane >> 4) << 3) + (lane & 7);   // x4 over two n-tiles
    const int b_h = (lane >> 3) & 1;

    int buf = 0;
    for (int it = 0; it < iters; ++it) {
        if (it + 1 < iters) { CP_WAIT(1); } else { CP_WAIT(0); }
        __syncthreads();
        if (it + 2 < iters) {
            int nb = buf + 2; if (nb >= 3) nb -= 3;
            gemm_load_stage(Ah0, Al0, Bh0, Bl0, K, (it + 2) * 32,
                            sb + nb * GSTAGE, tid);
            CP_COMMIT();
        }

        uint32_t sbuf = sb + buf * GSTAGE;
#pragma unroll
        for (int s = 0; s < 2; s++) {
            uint32_t ah[4][4], al[4][4];
#pragma unroll
            for (int mi = 0; mi < 4; mi++) {
                int row = wm * 64 + mi * 16 + a_r;
                int ch  = s * 2 + a_h;
                uint32_t off = row * 64 + ((ch ^ ((row >> 1) & 3)) << 4);
                ldsm_x4(ah[mi], sbuf + SM_AH + off);
                ldsm_x4(al[mi], sbuf + SM_AL + off);
            }
            uint32_t bh[8][2], bl[8][2];
#pragma unroll
            for (int ni2 = 0; ni2 < 4; ni2++) {
                int row = wn * 64 + ni2 * 16 + b_r;
                int ch  = s * 2 + b_h;
                uint32_t off = row * 64 + ((ch ^ ((row >> 1) & 3)) << 4);
                ldsm_x4(&bh[ni2 * 2][0], sbuf + SM_BH + off);
                ldsm_x4(&bl[ni2 * 2][0], sbuf + SM_BL + off);
            }
#pragma unroll
            for (int mi = 0; mi < 4; mi++)
#pragma unroll
                for (int ni = 0; ni < 8; ni++) {
                    mma_bf16(acc[mi][ni], ah[mi], bh[ni]);
                    mma_bf16(acc[mi][ni], ah[mi], bl[ni]);
                    mma_bf16(acc[mi][ni], al[mi], bh[ni]);
                }
        }
        buf++; if (buf >= 3) buf = 0;
    }

    const int r0 = lane >> 2;
    const int c0 = (lane & 3) * 2;
#pragma unroll
    for (int ni = 0; ni < 8; ni++) {
        int col = n0 + wn * 64 + ni * 8 + c0;
        float2 bv = *(const float2*)(bias + col);
#pragma unroll
        for (int mi = 0; mi < 4; mi++) {
            int row = m0 + wm * 64 + mi * 16 + r0;
            float v00 = acc[mi][ni][0] + bv.x, v01 = acc[mi][ni][1] + bv.y;
            float v10 = acc[mi][ni][2] + bv.x, v11 = acc[mi][ni][3] + bv.y;
            if (EPI == 0) {
                *(float2*)(C + (size_t)row * N + col)       = make_float2(v00, v01);
                *(float2*)(C + (size_t)(row + 8) * N + col) = make_float2(v10, v11);
            } else {
                float h00 = bf16_rt(v00), h01 = bf16_rt(v01);
                float h10 = bf16_rt(v10), h11 = bf16_rt(v11);
                *(uint32_t*)(Ch + (size_t)row * N + col)       = pack_bf2(h00, h01);
                *(uint32_t*)(Ch + (size_t)(row + 8) * N + col) = pack_bf2(h10, h11);
                *(uint32_t*)(Cl + (size_t)row * N + col)       = pack_bf2(v00 - h00, v01 - h01);
                *(uint32_t*)(Cl + (size_t)(row + 8) * N + col) = pack_bf2(v10 - h10, v11 - h11);
            }
        }
    }
}

__global__ __launch_bounds__(256)
void gemm_hmma(const __nv_bfloat16* __restrict__ Ah, const __nv_bfloat16* __restrict__ Al,
               const __nv_bfloat16* __restrict__ Bh, const __nv_bfloat16* __restrict__ Bl,
               const float* __restrict__ bias, float* __restrict__ C, int N, int K)
{
    gemm_body<0>(Ah, Al, Bh, Bl, bias, C, nullptr, nullptr, N, K);
}
__global__ __launch_bounds__(256)
void gemm_hmma_split(const __nv_bfloat16* __restrict__ Ah, const __nv_bfloat16* __restrict__ Al,
                     const __nv_bfloat16* __restrict__ Bh, const __nv_bfloat16* __restrict__ Bl,
                     const float* __restrict__ bias,
                     __nv_bfloat16* __restrict__ Ch, __nv_bfloat16* __restrict__ Cl, int N, int K)
{
    gemm_body<1>(Ah, Al, Bh, Bl, bias, nullptr, Ch, Cl, N, K);
}

// ---------------------------------------------------------------------------
// HMMA flash attention, causal. Q tile 128 x 4 warps; K/V tiles 64, 2-stage.
// P is hi/lo split for the PV product (3-term) to keep rel_err ~1e-5.
// ---------------------------------------------------------------------------
#define ASQH 0
#define ASQL 16384
#define ASTG 32768
#define AKH  0
#define AKL  8192
#define AVH  16384
#define AVL  24576
#define ASMEM 98304
#define LOG2E_8 0.18033688f   // log2(e)/8

__device__ __forceinline__ void stage_kv(const __nv_bfloat16* kh, const __nv_bfloat16* kl,
                                         const __nv_bfloat16* vh, const __nv_bfloat16* vl,
                                         uint32_t sdst, int tid)
{
#pragma unroll
    for (int i = 0; i < 4; i++) {
        int idx = i * 128 + tid;      // 0..511
        int r = idx >> 3, c = idx & 7;
        uint32_t so = r * 128 + ((c ^ (r & 7)) << 4);
        size_t go = (size_t)r * RSQKV + c * 8;
        CP_ASYNC16(sdst + AKH + so, kh + go);
        CP_ASYNC16(sdst + AKL + so, kl + go);
        CP_ASYNC16(sdst + AVH + so, vh + go);
        CP_ASYNC16(sdst + AVL + so, vl + go);
    }
}

__global__ __launch_bounds__(128)
void attn_hmma(const __nv_bfloat16* __restrict__ qkvh, const __nv_bfloat16* __restrict__ qkvl,
               __nv_bfloat16* __restrict__ xh, __nv_bfloat16* __restrict__ xl)
{
    extern __shared__ char smem[];
    uint32_t sb = smem_u32(smem);
    const int tid = threadIdx.x, warp = tid >> 5, lane = tid & 31;
    const int qt = (int)(gridDim.x - 1) - (int)blockIdx.x;     // big tiles first
    const int bh = blockIdx.y;
    const int b = bh >> 4, h = bh & 15;
    const int q0 = qt * 128;

    const size_t bhoff = (size_t)b * SEQ * RSQKV + h * HDIM;
    const __nv_bfloat16* qh_g = qkvh + bhoff + (size_t)q0 * RSQKV;
    const __nv_bfloat16* ql_g = qkvl + bhoff + (size_t)q0 * RSQKV;
    const __nv_bfloat16* kh_g = qkvh + bhoff + EMBED;
    const __nv_bfloat16* kl_g = qkvl + bhoff + EMBED;
    const __nv_bfloat16* vh_g = qkvh + bhoff + 2 * EMBED;
    const __nv_bfloat16* vl_g = qkvl + bhoff + 2 * EMBED;

    // stage Q (hi+lo)
#pragma unroll
    for (int i = 0; i < 8; i++) {
        int idx = i * 128 + tid;
        int r = idx >> 3, c = idx & 7;
        uint32_t so = r * 128 + ((c ^ (r & 7)) << 4);
        size_t go = (size_t)r * RSQKV + c * 8;
        CP_ASYNC16(sb + ASQH + so, qh_g + go);
        CP_ASYNC16(sb + ASQL + so, ql_g + go);
    }
    CP_COMMIT();
    const int kts = 2 * qt + 2;
    stage_kv(kh_g, kl_g, vh_g, vl_g, sb + ASTG, tid);
    CP_COMMIT();

    CP_WAIT(1);                 // Q ready
    __syncthreads();

    // preload Qh fragments (reg-resident)
    uint32_t qfh[2][4][4];
#pragma unroll
    for (int mi = 0; mi < 2; mi++)
#pragma unroll
        for (int kc = 0; kc < 4; kc++) {
            int row = warp * 32 + mi * 16 + (lane & 15);
            int ch  = kc * 2 + (lane >> 4);
            ldsm_x4(qfh[mi][kc], sb + ASQH + row * 128 + ((ch ^ (row & 7)) << 4));
        }

    float m_s[2][2], l_s[2][2], O[2][8][4];
#pragma unroll
    for (int mi = 0; mi < 2; mi++)
#pragma unroll
        for (int hh = 0; hh < 2; hh++) { m_s[mi][hh] = -1e30f; l_s[mi][hh] = 0.f; }
#pragma unroll
    for (int mi = 0; mi < 2; mi++)
#pragma unroll
        for (int nd = 0; nd < 8; nd++)
#pragma unroll
            for (int e = 0; e < 4; e++) O[mi][nd][e] = 0.f;

    for (int kt = 0; kt < kts; ++kt) {
        uint32_t sbuf = sb + ASTG + (kt & 1) * 32768;
        if (kt == 0) { CP_WAIT(0); __syncthreads(); }
        if (kt + 1 < kts) {
            stage_kv(kh_g + (size_t)(kt + 1) * 64 * RSQKV, kl_g + (size_t)(kt + 1) * 64 * RSQKV,
                     vh_g + (size_t)(kt + 1) * 64 * RSQKV, vl_g + (size_t)(kt + 1) * 64 * RSQKV,
                     sb + ASTG + ((kt + 1) & 1) * 32768, tid);
            CP_COMMIT();
        }

        // ---- S = Q K^T (bf16 split, 3 terms) ----
        float S[2][8][4];
#pragma unroll
        for (int mi = 0; mi < 2; mi++)
#pragma unroll
            for (int ni = 0; ni < 8; ni++)
#pragma unroll
                for (int e = 0; e < 4; e++) S[mi][ni][e] = 0.f;

#pragma unroll
        for (int kc = 0; kc < 4; kc++) {
            uint32_t qfl[2][4];
#pragma unroll
            for (int mi = 0; mi < 2; mi++) {
                int row = warp * 32 + mi * 16 + (lane & 15);
                int ch  = kc * 2 + (lane >> 4);
                ldsm_x4(qfl[mi], sb + ASQL + row * 128 + ((ch ^ (row & 7)) << 4));
            }
#pragma unroll
            for (int ni = 0; ni < 8; ni++) {
                uint32_t kfh[2], kfl[2];
                int krow = ni * 8 + (lane & 7);
                int ch   = kc * 2 + ((lane >> 3) & 1);
                uint32_t koff = krow * 128 + ((ch ^ (krow & 7)) << 4);
                ldsm_x2(kfh, sbuf + AKH + koff);
                ldsm_x2(kfl, sbuf + AKL + koff);
#pragma unroll
                for (int mi = 0; mi < 2; mi++) {
                    mma_bf16(S[mi][ni], qfh[mi][kc], kfh);
                    mma_bf16(S[mi][ni], qfh[mi][kc], kfl);
                    mma_bf16(S[mi][ni], qfl[mi], kfh);
                }
            }
        }

        // ---- online softmax (base-2 domain) ----
        const int k0 = kt * 64;
        const bool need_mask = (kt >= 2 * qt);
#pragma unroll
        for (int mi = 0; mi < 2; mi++)
#pragma unroll
            for (int hh = 0; hh < 2; hh++) {
                int row = q0 + warp * 32 + mi * 16 + (lane >> 2) + hh * 8;
                float mx = -1e30f;
#pragma unroll
                for (int ni = 0; ni < 8; ni++)
#pragma unroll
                    for (int e = 0; e < 2; e++) {
                        float v = S[mi][ni][hh * 2 + e] * LOG2E_8;
                        if (need_mask) {
                            int col = k0 + ni * 8 + (lane & 3) * 2 + e;
                            if (col > row) v = -1e30f;
                        }
                        S[mi][ni][hh * 2 + e] = v;
                        mx = fmaxf(mx, v);
                    }
                mx = fmaxf(mx, __shfl_xor_sync(0xffffffffu, mx, 1));
                mx = fmaxf(mx, __shfl_xor_sync(0xffffffffu, mx, 2));
                float mnew = fmaxf(m_s[mi][hh], mx);
                float al = ex2f(m_s[mi][hh] - mnew);
                float sum = 0.f;
#pragma unroll
                for (int ni = 0; ni < 8; ni++)
#pragma unroll
                    for (int e = 0; e < 2; e++) {
                        float p = ex2f(S[mi][ni][hh * 2 + e] - mnew);
                        S[mi][ni][hh * 2 + e] = p;
                        sum += p;
                    }
                sum += __shfl_xor_sync(0xffffffffu, sum, 1);
                sum += __shfl_xor_sync(0xffffffffu, sum, 2);
                l_s[mi][hh] = l_s[mi][hh] * al + sum;
                m_s[mi][hh] = mnew;
#pragma unroll
                for (int nd = 0; nd < 8; nd++) {
                    O[mi][nd][hh * 2 + 0] *= al;
                    O[mi][nd][hh * 2 + 1] *= al;
                }
            }

        // ---- O += P V (P hi/lo split, 3 terms; V via ldmatrix.trans) ----
#pragma unroll
        for (int j = 0; j < 4; j++) {
            uint32_t pfh[2][4], pfl[2][4];
#pragma unroll
            for (int mi = 0; mi < 2; mi++) {
                float p00 = S[mi][2 * j][0],     p01 = S[mi][2 * j][1];
                float p02 = S[mi][2 * j][2],     p03 = S[mi][2 * j][3];
                float p10 = S[mi][2 * j + 1][0], p11 = S[mi][2 * j + 1][1];
                float p12 = S[mi][2 * j + 1][2], p13 = S[mi][2 * j + 1][3];
                float h00 = bf16_rt(p00), h01 = bf16_rt(p01);
                float h02 = bf16_rt(p02), h03 = bf16_rt(p03);
                float h10 = bf16_rt(p10), h11 = bf16_rt(p11);
                float h12 = bf16_rt(p12), h13 = bf16_rt(p13);
                pfh[mi][0] = pack_bf2(h00, h01);
                pfh[mi][1] = pack_bf2(h02, h03);
                pfh[mi][2] = pack_bf2(h10, h11);
                pfh[mi][3] = pack_bf2(h12, h13);
                pfl[mi][0] = pack_bf2(p00 - h00, p01 - h01);
                pfl[mi][1] = pack_bf2(p02 - h02, p03 - h03);
                pfl[mi][2] = pack_bf2(p10 - h10, p11 - h11);
                pfl[mi][3] = pack_bf2(p12 - h12, p13 - h13);
            }
#pragma unroll
            for (int nd = 0; nd < 8; nd++) {
                uint32_t vfh[2], vfl[2];
                int vrow = j * 16 + (lane & 15);
                uint32_t voff = vrow * 128 + ((nd ^ (vrow & 7)) << 4);
                ldsm_x2_t(vfh, sbuf + AVH + voff);
                ldsm_x2_t(vfl, sbuf + AVL + voff);
#pragma unroll
                for (int mi = 0; mi < 2; mi++) {
                    mma_bf16(O[mi][nd], pfh[mi], vfh);
                    mma_bf16(O[mi][nd], pfh[mi], vfl);
                    mma_bf16(O[mi][nd], pfl[mi], vfh);
                }
            }
        }

        if (kt + 1 < kts) { CP_WAIT(0); }
        __syncthreads();
    }

    // ---- epilogue: normalize, split to bf16 hi/lo ----
#pragma unroll
    for (int mi = 0; mi < 2; mi++)
#pragma unroll
        for (int hh = 0; hh < 2; hh++) {
            float inv = 1.f / l_s[mi][hh];
            int row = q0 + warp * 32 + mi * 16 + (lane >> 2) + hh * 8;
            size_t base = (size_t)(b * SEQ + row) * EMBED + h * HDIM;
#pragma unroll
            for (int nd = 0; nd < 8; nd++) {
                int d = nd * 8 + (lane & 3) * 2;
                float v0 = O[mi][nd][hh * 2 + 0] * inv;
                float v1 = O[mi][nd][hh * 2 + 1] * inv;
                float h0 = bf16_rt(v0);
                float h1 = bf16_rt(v1);
                *(uint32_t*)(xh + base + d) = pack_bf2(h0, h1);
                *(uint32_t*)(xl + base + d) = pack_bf2(v0 - h0, v1 - h1);
            }
        }
}

// ---------------------------------------------------------------------------
extern "C" void kernel_launch(void* const* d_in, const int* in_sizes, int n_in,
                              void* d_out, int out_size)
{
    const float* hs     = (const float*)d_in[0];
    const float* attn_w = (const float*)d_in[1];
    const float* attn_b = (const float*)d_in[2];
    const float* proj_w = (const float*)d_in[3];
    const float* proj_b = (const float*)d_in[4];
    float* out = (float*)d_out;

    __nv_bfloat16 *Ah, *Al, *Wqh, *Wql, *Wph, *Wpl, *QKVh, *QKVl, *Xh, *Xl;
    cudaGetSymbolAddress((void**)&Ah,   g_Ah);
    cudaGetSymbolAddress((void**)&Al,   g_Al);
    cudaGetSymbolAddress((void**)&Wqh,  g_Wqh);
    cudaGetSymbolAddress((void**)&Wql,  g_Wql);
    cudaGetSymbolAddress((void**)&Wph,  g_Wph);
    cudaGetSymbolAddress((void**)&Wpl,  g_Wpl);
    cudaGetSymbolAddress((void**)&QKVh, g_QKVh);
    cudaGetSymbolAddress((void**)&QKVl, g_QKVl);
    cudaGetSymbolAddress((void**)&Xh,   g_Xh);
    cudaGetSymbolAddress((void**)&Xl,   g_Xl);

    cudaFuncSetAttribute(gemm_hmma, cudaFuncAttributeMaxDynamicSharedMemorySize, GSMEM);
    cudaFuncSetAttribute(gemm_hmma_split, cudaFuncAttributeMaxDynamicSharedMemorySize, GSMEM);
    cudaFuncSetAttribute(attn_hmma, cudaFuncAttributeMaxDynamicSharedMemorySize, ASMEM);

    // 0) prepare split operands
    split_f32<<<2048, 256>>>(hs, Ah, Al, MTOT * EMBED / 4);
    transpose_split<<<dim3(3 * EMBED / 32, EMBED / 32), dim3(32, 8)>>>(attn_w, Wqh, Wql, EMBED, 3 * EMBED);
    transpose_split<<<dim3(EMBED / 32, EMBED / 32), dim3(32, 8)>>>(proj_w, Wph, Wpl, EMBED, EMBED);

    // 1) QKV projection -> bf16 hi/lo qkv  (N tiles of 256)
    gemm_hmma_split<<<dim3(3 * EMBED / 256, MTOT / 128), 256, GSMEM>>>(
        Ah, Al, Wqh, Wql, attn_b, QKVh, QKVl, 3 * EMBED, EMBED);

    // 2) HMMA causal flash attention -> bf16 hi/lo X
    attn_hmma<<<dim3(SEQ / 128, BATCH * HEADS), 128, ASMEM>>>(QKVh, QKVl, Xh, Xl);

    // 3) output projection (fp32 out)
    gemm_hmma<<<dim3(EMBED / 256, MTOT / 128), 256, GSMEM>>>(
        Xh, Xl, Wph, Wpl, proj_b, out, EMBED, EMBED);
}

// round 12
// speedup vs baseline: 2.4955x; 2.4955x over previous
#include <cuda_runtime.h>
#include <cuda_fp16.h>
#include <cstdint>

#define EMBED 1024
#define SEQ   2048
#define BATCH 4
#define HEADS 16
#define HDIM  64
#define MTOT  (BATCH * SEQ)          // 8192 rows
#define RSQKV (3 * EMBED)            // qkv row stride (elements)

// ---------------- scratch (static device globals; allocation-free) ----------
__device__ __half  g_A[(size_t)MTOT * EMBED];            // hs fp16
__device__ __half  g_Wq[(size_t)3 * EMBED * EMBED];      // qkv W^T fp16 [N][K]
__device__ __half  g_Wp[(size_t)EMBED * EMBED];          // proj W^T fp16
__device__ __half  g_QKV[(size_t)MTOT * 3 * EMBED];      // qkv fp16
__device__ __half  g_X[(size_t)MTOT * EMBED];            // attn out fp16

// ---------------- helpers ----------------------------------------------------
__device__ __forceinline__ uint32_t smem_u32(const void* p) {
    uint32_t a;
    asm("{ .reg .u64 t; cvta.to.shared.u64 t, %1; cvt.u32.u64 %0, t; }" : "=r"(a) : "l"(p));
    return a;
}
#define CP_ASYNC16(dst, src) \
    asm volatile("cp.async.cg.shared.global [%0], [%1], 16;" :: "r"(dst), "l"(src))
#define CP_COMMIT() asm volatile("cp.async.commit_group;")
#define CP_WAIT(n)  asm volatile("cp.async.wait_group %0;" :: "n"(n))

__device__ __forceinline__ void ldsm_x4(uint32_t* r, uint32_t addr) {
    asm volatile("ldmatrix.sync.aligned.m8n8.x4.shared.b16 {%0,%1,%2,%3}, [%4];"
                 : "=r"(r[0]), "=r"(r[1]), "=r"(r[2]), "=r"(r[3]) : "r"(addr));
}
__device__ __forceinline__ void ldsm_x2(uint32_t* r, uint32_t addr) {
    asm volatile("ldmatrix.sync.aligned.m8n8.x2.shared.b16 {%0,%1}, [%2];"
                 : "=r"(r[0]), "=r"(r[1]) : "r"(addr));
}
__device__ __forceinline__ void ldsm_x2_t(uint32_t* r, uint32_t addr) {
    asm volatile("ldmatrix.sync.aligned.m8n8.x2.trans.shared.b16 {%0,%1}, [%2];"
                 : "=r"(r[0]), "=r"(r[1]) : "r"(addr));
}
__device__ __forceinline__ void mma_f16(float* d, const uint32_t* a, const uint32_t* b) {
    asm volatile("mma.sync.aligned.m16n8k16.row.col.f32.f16.f16.f32 "
                 "{%0,%1,%2,%3}, {%4,%5,%6,%7}, {%8,%9}, {%0,%1,%2,%3};"
                 : "+f"(d[0]), "+f"(d[1]), "+f"(d[2]), "+f"(d[3])
                 : "r"(a[0]), "r"(a[1]), "r"(a[2]), "r"(a[3]), "r"(b[0]), "r"(b[1]));
}
__device__ __forceinline__ float ex2f(float x) {
    float y; asm("ex2.approx.f32 %0, %1;" : "=f"(y) : "f"(x)); return y;
}
// pack {lo=a, hi=b} fp32 -> fp16x2
__device__ __forceinline__ uint32_t pack_h2(float a, float b) {
    uint32_t r; asm("cvt.rn.f16x2.f32 %0, %1, %2;" : "=r"(r) : "f"(b), "f"(a)); return r;
}

// ---------------------------------------------------------------------------
// convert fp32 -> fp16
// ---------------------------------------------------------------------------
__global__ void cvt_f32_f16(const float* __restrict__ x, __half* __restrict__ y, int n4)
{
    int i = blockIdx.x * blockDim.x + threadIdx.x;
    int stride = gridDim.x * blockDim.x;
    for (; i < n4; i += stride) {
        float4 v = ((const float4*)x)[i];
        uint2 o;
        o.x = pack_h2(v.x, v.y);
        o.y = pack_h2(v.z, v.w);
        ((uint2*)y)[i] = o;
    }
}

// ---------------------------------------------------------------------------
// transpose + convert: W[K][N] fp32 -> Wt[N][K] fp16
// ---------------------------------------------------------------------------
__global__ void transpose_cvt(const float* __restrict__ W, __half* __restrict__ T,
                              int K, int N)
{
    __shared__ float t[32][33];
    int tx = threadIdx.x, ty = threadIdx.y;
#pragma unroll
    for (int j = 0; j < 4; j++) {
        int k = blockIdx.y * 32 + ty + j * 8;
        int n = blockIdx.x * 32 + tx;
        t[ty + j * 8][tx] = W[(size_t)k * N + n];
    }
    __syncthreads();
#pragma unroll
    for (int j = 0; j < 4; j++) {
        int n = blockIdx.x * 32 + ty + j * 8;
        int k = blockIdx.y * 32 + tx;
        T[(size_t)n * K + k] = __float2half_rn(t[tx][ty + j * 8]);
    }
}

// ---------------------------------------------------------------------------
// fp16 HMMA GEMM. block 128x128x32, 256 thr, warp tile 64x32, 2-stage.
// EPI=0: fp32 out + bias.  EPI=1: fp16 out + bias.
// smem stage: A 8K | B 8K = 16K; 2 stages = 32K. (R6 pipeline shape)
// ---------------------------------------------------------------------------
#define GSTAGE 16384
#define GTILE  8192
#define GSMEM  (2 * GSTAGE)

__device__ __forceinline__ void gemm_load_stage(
    const __half* __restrict__ A, const __half* __restrict__ B,
    int K, int k0, uint32_t sdst, int tid)
{
    const __half* srcs[2] = { A, B };
#pragma unroll
    for (int i = 0; i < 4; i++) {
        int idx = i * 256 + tid;          // 0..1023
        int tile = idx >> 9;              // 0..1
        int r    = (idx >> 2) & 127;
        int c    = idx & 3;
        const char* g = (const char*)(srcs[tile] + (size_t)r * K + k0) + c * 16;
        uint32_t s = sdst + tile * GTILE + r * 64 + ((c ^ ((r >> 1) & 3)) << 4);
        CP_ASYNC16(s, g);
    }
}

template <int EPI>
__device__ __forceinline__ void gemm_body(
    const __half* __restrict__ A, const __half* __restrict__ B,
    const float* __restrict__ bias, float* __restrict__ C,
    __half* __restrict__ Ch, int N, int K)
{
    extern __shared__ char smem[];
    uint32_t sb = smem_u32(smem);
    const int tid  = threadIdx.x;
    const int warp = tid >> 5, lane = tid & 31;
    const int wm = warp >> 2, wn = warp & 3;

    const int m0 = blockIdx.y * 128;
    const int n0 = blockIdx.x * 128;
    const __half* A0 = A + (size_t)m0 * K;
    const __half* B0 = B + (size_t)n0 * K;

    float acc[4][4][4];
#pragma unroll
    for (int i = 0; i < 4; i++)
#pragma unroll
        for (int j = 0; j < 4; j++)
#pragma unroll
            for (int k = 0; k < 4; k++) acc[i][j][k] = 0.f;

    const int iters = K >> 5;
    gemm_load_stage(A0, B0, K, 0, sb, tid);
    CP_COMMIT();

    const int a_r = lane & 15;
    const int a_h = lane >> 4;
    const int b_r = lane & 7;
    const int b_h = (lane >> 3) & 1;

    for (int it = 0; it < iters; ++it) {
        uint32_t sbuf = sb + (it & 1) * GSTAGE;
        if (it + 1 < iters) {
            gemm_load_stage(A0, B0, K, (it + 1) * 32, sb + ((it + 1) & 1) * GSTAGE, tid);
            CP_COMMIT();
            CP_WAIT(1);
        } else {
            CP_WAIT(0);
        }
        __syncthreads();

#pragma unroll
        for (int s = 0; s < 2; s++) {
            uint32_t af[4][4];
#pragma unroll
            for (int mi = 0; mi < 4; mi++) {
                int row = wm * 64 + mi * 16 + a_r;
                int ch  = s * 2 + a_h;
                uint32_t off = row * 64 + ((ch ^ ((row >> 1) & 3)) << 4);
                ldsm_x4(af[mi], sbuf + 0 * GTILE + off);
            }
            uint32_t bf[4][2];
#pragma unroll
            for (int ni = 0; ni < 4; ni++) {
                int row = wn * 32 + ni * 8 + b_r;
                int ch  = s * 2 + b_h;
                uint32_t off = row * 64 + ((ch ^ ((row >> 1) & 3)) << 4);
                ldsm_x2(bf[ni], sbuf + 1 * GTILE + off);
            }
#pragma unroll
            for (int mi = 0; mi < 4; mi++)
#pragma unroll
                for (int ni = 0; ni < 4; ni++)
                    mma_f16(acc[mi][ni], af[mi], bf[ni]);
        }
        __syncthreads();
    }

    const int r0 = lane >> 2;
    const int c0 = (lane & 3) * 2;
#pragma unroll
    for (int ni = 0; ni < 4; ni++) {
        int col = n0 + wn * 32 + ni * 8 + c0;
        float2 bv = *(const float2*)(bias + col);
#pragma unroll
        for (int mi = 0; mi < 4; mi++) {
            int row = m0 + wm * 64 + mi * 16 + r0;
            float v00 = acc[mi][ni][0] + bv.x, v01 = acc[mi][ni][1] + bv.y;
            float v10 = acc[mi][ni][2] + bv.x, v11 = acc[mi][ni][3] + bv.y;
            if (EPI == 0) {
                *(float2*)(C + (size_t)row * N + col)       = make_float2(v00, v01);
                *(float2*)(C + (size_t)(row + 8) * N + col) = make_float2(v10, v11);
            } else {
                *(uint32_t*)(Ch + (size_t)row * N + col)       = pack_h2(v00, v01);
                *(uint32_t*)(Ch + (size_t)(row + 8) * N + col) = pack_h2(v10, v11);
            }
        }
    }
}

__global__ __launch_bounds__(256, 2)
void gemm_f16(const __half* __restrict__ A, const __half* __restrict__ B,
              const float* __restrict__ bias, float* __restrict__ C, int N, int K)
{
    gemm_body<0>(A, B, bias, C, nullptr, N, K);
}
__global__ __launch_bounds__(256, 2)
void gemm_f16_h(const __half* __restrict__ A, const __half* __restrict__ B,
                const float* __restrict__ bias, __half* __restrict__ Ch, int N, int K)
{
    gemm_body<1>(A, B, bias, nullptr, Ch, N, K);
}

// ---------------------------------------------------------------------------
// fp16 HMMA flash attention, causal. Q tile 128 x 4 warps; K/V tiles 64, 2-stage.
// smem: Q 16K | stage0 {K 8K, V 8K} | stage1 {...} = 48K
// rows are 128B (64 fp16), 16B-chunk swizzle c ^ (r&7)
// ---------------------------------------------------------------------------
#define ASQ  0
#define ASTG 16384
#define AK   0
#define AV   8192
#define ASTGSZ 16384
#define ASMEM 49152
#define LOG2E_8 0.18033688f   // log2(e)/8

__device__ __forceinline__ void stage_kv(const __half* k, const __half* v,
                                         uint32_t sdst, int tid)
{
#pragma unroll
    for (int i = 0; i < 4; i++) {
        int idx = i * 128 + tid;      // 0..511
        int r = idx >> 3, c = idx & 7;
        uint32_t so = r * 128 + ((c ^ (r & 7)) << 4);
        size_t go = (size_t)r * RSQKV + c * 8;
        CP_ASYNC16(sdst + AK + so, k + go);
        CP_ASYNC16(sdst + AV + so, v + go);
    }
}

__global__ __launch_bounds__(128)
void attn_f16(const __half* __restrict__ qkv, __half* __restrict__ x)
{
    extern __shared__ char smem[];
    uint32_t sb = smem_u32(smem);
    const int tid = threadIdx.x, warp = tid >> 5, lane = tid & 31;
    const int qt = (int)(gridDim.x - 1) - (int)blockIdx.x;     // big tiles first
    const int bh = blockIdx.y;
    const int b = bh >> 4, h = bh & 15;
    const int q0 = qt * 128;

    const size_t bhoff = (size_t)b * SEQ * RSQKV + h * HDIM;
    const __half* q_g = qkv + bhoff + (size_t)q0 * RSQKV;
    const __half* k_g = qkv + bhoff + EMBED;
    const __half* v_g = qkv + bhoff + 2 * EMBED;

    // stage Q: 128 rows x 8 chunks = 1024 chunks
#pragma unroll
    for (int i = 0; i < 8; i++) {
        int idx = i * 128 + tid;
        int r = idx >> 3, c = idx & 7;
        uint32_t so = r * 128 + ((c ^ (r & 7)) << 4);
        CP_ASYNC16(sb + ASQ + so, q_g + (size_t)r * RSQKV + c * 8);
    }
    CP_COMMIT();
    const int kts = 2 * qt + 2;
    stage_kv(k_g, v_g, sb + ASTG, tid);
    CP_COMMIT();

    CP_WAIT(1);                 // Q ready
    __syncthreads();

    // preload Q fragments (reg-resident, all 4 k-chunks)
    uint32_t qf[2][4][4];
#pragma unroll
    for (int mi = 0; mi < 2; mi++)
#pragma unroll
        for (int kc = 0; kc < 4; kc++) {
            int row = warp * 32 + mi * 16 + (lane & 15);
            int ch  = kc * 2 + (lane >> 4);
            ldsm_x4(qf[mi][kc], sb + ASQ + row * 128 + ((ch ^ (row & 7)) << 4));
        }

    float m_s[2][2], l_s[2][2], O[2][8][4];
#pragma unroll
    for (int mi = 0; mi < 2; mi++)
#pragma unroll
        for (int hh = 0; hh < 2; hh++) { m_s[mi][hh] = -1e30f; l_s[mi][hh] = 0.f; }
#pragma unroll
    for (int mi = 0; mi < 2; mi++)
#pragma unroll
        for (int nd = 0; nd < 8; nd++)
#pragma unroll
            for (int e = 0; e < 4; e++) O[mi][nd][e] = 0.f;

    for (int kt = 0; kt < kts; ++kt) {
        uint32_t sbuf = sb + ASTG + (kt & 1) * ASTGSZ;
        if (kt == 0) { CP_WAIT(0); __syncthreads(); }
        if (kt + 1 < kts) {
            stage_kv(k_g + (size_t)(kt + 1) * 64 * RSQKV,
                     v_g + (size_t)(kt + 1) * 64 * RSQKV,
                     sb + ASTG + ((kt + 1) & 1) * ASTGSZ, tid);
            CP_COMMIT();
        }

        // ---- S = Q K^T ----
        float S[2][8][4];
#pragma unroll
        for (int mi = 0; mi < 2; mi++)
#pragma unroll
            for (int ni = 0; ni < 8; ni++)
#pragma unroll
                for (int e = 0; e < 4; e++) S[mi][ni][e] = 0.f;

#pragma unroll
        for (int kc = 0; kc < 4; kc++) {
#pragma unroll
            for (int ni = 0; ni < 8; ni++) {
                uint32_t kf[2];
                int krow = ni * 8 + (lane & 7);
                int ch   = kc * 2 + ((lane >> 3) & 1);
                ldsm_x2(kf, sbuf + AK + krow * 128 + ((ch ^ (krow & 7)) << 4));
#pragma unroll
                for (int mi = 0; mi < 2; mi++)
                    mma_f16(S[mi][ni], qf[mi][kc], kf);
            }
        }

        // ---- online softmax (base-2 domain) ----
        const int k0 = kt * 64;
        const bool need_mask = (kt >= 2 * qt);
#pragma unroll
        for (int mi = 0; mi < 2; mi++)
#pragma unroll
            for (int hh = 0; hh < 2; hh++) {
                int row = q0 + warp * 32 + mi * 16 + (lane >> 2) + hh * 8;
                float mx = -1e30f;
#pragma unroll
                for (int ni = 0; ni < 8; ni++)
#pragma unroll
                    for (int e = 0; e < 2; e++) {
                        float v = S[mi][ni][hh * 2 + e] * LOG2E_8;
                        if (need_mask) {
                            int col = k0 + ni * 8 + (lane & 3) * 2 + e;
                            if (col > row) v = -1e30f;
                        }
                        S[mi][ni][hh * 2 + e] = v;
                        mx = fmaxf(mx, v);
                    }
                mx = fmaxf(mx, __shfl_xor_sync(0xffffffffu, mx, 1));
                mx = fmaxf(mx, __shfl_xor_sync(0xffffffffu, mx, 2));
                float mnew = fmaxf(m_s[mi][hh], mx);
                float al = ex2f(m_s[mi][hh] - mnew);
                float sum = 0.f;
#pragma unroll
                for (int ni = 0; ni < 8; ni++)
#pragma unroll
                    for (int e = 0; e < 2; e++) {
                        float p = ex2f(S[mi][ni][hh * 2 + e] - mnew);
                        S[mi][ni][hh * 2 + e] = p;
                        sum += p;
                    }
                sum += __shfl_xor_sync(0xffffffffu, sum, 1);
                sum += __shfl_xor_sync(0xffffffffu, sum, 2);
                l_s[mi][hh] = l_s[mi][hh] * al + sum;
                m_s[mi][hh] = mnew;
#pragma unroll
                for (int nd = 0; nd < 8; nd++) {
                    O[mi][nd][hh * 2 + 0] *= al;
                    O[mi][nd][hh * 2 + 1] *= al;
                }
            }

        // ---- O += P V (P fp16, V via ldmatrix.trans) ----
#pragma unroll
        for (int j = 0; j < 4; j++) {
            uint32_t pf[2][4];
#pragma unroll
            for (int mi = 0; mi < 2; mi++) {
                pf[mi][0] = pack_h2(S[mi][2 * j][0],     S[mi][2 * j][1]);
                pf[mi][1] = pack_h2(S[mi][2 * j][2],     S[mi][2 * j][3]);
                pf[mi][2] = pack_h2(S[mi][2 * j + 1][0], S[mi][2 * j + 1][1]);
                pf[mi][3] = pack_h2(S[mi][2 * j + 1][2], S[mi][2 * j + 1][3]);
            }
#pragma unroll
            for (int nd = 0; nd < 8; nd++) {
                uint32_t vf[2];
                int vrow = j * 16 + (lane & 15);
                ldsm_x2_t(vf, sbuf + AV + vrow * 128 + ((nd ^ (vrow & 7)) << 4));
#pragma unroll
                for (int mi = 0; mi < 2; mi++)
                    mma_f16(O[mi][nd], pf[mi], vf);
            }
        }

        if (kt + 1 < kts) { CP_WAIT(0); }
        __syncthreads();
    }

    // ---- epilogue: normalize, convert to fp16 ----
#pragma unroll
    for (int mi = 0; mi < 2; mi++)
#pragma unroll
        for (int hh = 0; hh < 2; hh++) {
            float inv = 1.f / l_s[mi][hh];
            int row = q0 + warp * 32 + mi * 16 + (lane >> 2) + hh * 8;
            size_t base = (size_t)(b * SEQ + row) * EMBED + h * HDIM;
#pragma unroll
            for (int nd = 0; nd < 8; nd++) {
                int d = nd * 8 + (lane & 3) * 2;
                *(uint32_t*)(x + base + d) =
                    pack_h2(O[mi][nd][hh * 2 + 0] * inv, O[mi][nd][hh * 2 + 1] * inv);
            }
        }
}

// ---------------------------------------------------------------------------
extern "C" void kernel_launch(void* const* d_in, const int* in_sizes, int n_in,
                              void* d_out, int out_size)
{
    const float* hs     = (const float*)d_in[0];
    const float* attn_w = (const float*)d_in[1];
    const float* attn_b = (const float*)d_in[2];
    const float* proj_w = (const float*)d_in[3];
    const float* proj_b = (const float*)d_in[4];
    float* out = (float*)d_out;

    __half *A, *Wq, *Wp, *QKV, *X;
    cudaGetSymbolAddress((void**)&A,   g_A);
    cudaGetSymbolAddress((void**)&Wq,  g_Wq);
    cudaGetSymbolAddress((void**)&Wp,  g_Wp);
    cudaGetSymbolAddress((void**)&QKV, g_QKV);
    cudaGetSymbolAddress((void**)&X,   g_X);

    cudaFuncSetAttribute(gemm_f16,   cudaFuncAttributeMaxDynamicSharedMemorySize, GSMEM);
    cudaFuncSetAttribute(gemm_f16_h, cudaFuncAttributeMaxDynamicSharedMemorySize, GSMEM);
    cudaFuncSetAttribute(attn_f16,   cudaFuncAttributeMaxDynamicSharedMemorySize, ASMEM);

    // 0) prepare fp16 operands
    cvt_f32_f16<<<2048, 256>>>(hs, A, MTOT * EMBED / 4);
    transpose_cvt<<<dim3(3 * EMBED / 32, EMBED / 32), dim3(32, 8)>>>(attn_w, Wq, EMBED, 3 * EMBED);
    transpose_cvt<<<dim3(EMBED / 32, EMBED / 32), dim3(32, 8)>>>(proj_w, Wp, EMBED, EMBED);

    // 1) QKV projection -> fp16 qkv
    gemm_f16_h<<<dim3(3 * EMBED / 128, MTOT / 128), 256, GSMEM>>>(
        A, Wq, attn_b, QKV, 3 * EMBED, EMBED);

    // 2) fp16 HMMA causal flash attention -> fp16 X
    attn_f16<<<dim3(SEQ / 128, BATCH * HEADS), 128, ASMEM>>>(QKV, X);

    // 3) output projection (fp32 out)
    gemm_f16<<<dim3(EMBED / 128, MTOT / 128), 256, GSMEM>>>(
        X, Wp, proj_b, out, EMBED, EMBED);
}